// round 14
// baseline (speedup 1.0000x reference)
#include <cuda_runtime.h>
#include <cstdint>
#include <cstddef>

// ---------------------------------------------------------------------------
// Problem constants
// ---------------------------------------------------------------------------
#define SEQ   512
#define BATCH 64
#define NHID  1024
#define NIN   1024
#define G4    4096   // 4*NHID

// Persistent recurrence config: 32 n-blocks (128 wide) x 8 k-slices (128 deep)
// 256 CTAs x 128 threads, ~99KB smem -> occupancy 2 (8 warps/SM), all 256
// CTAs fit in wave 1 (<= 148 SMs x 2) -> grid barrier deadlock-free.
#define NBLK   32
#define KSLICES 8
#define KSL    128
#define NCTA   256
#define PERS_THREADS 128

// tf32 smem tiles, stride 132 u32 (132 mod 32 = 4 -> frag banks 4*lq+lrm all
// distinct -> conflict-free fragment LDS)
#define TS_STRIDE 132
#define WSU_U32 (128 * TS_STRIDE)   // w_h slice [128 n][128 k]
#define HSU_U32 (64  * TS_STRIDE)   // h   slice [64 b][128 k]
#define PERS_SMEM_BYTES ((WSU_U32 + HSU_U32) * 4)  // 101376 B; 2/SM = 198.7KB < 227KB

// ---------------------------------------------------------------------------
// Scratch (static device globals; no dynamic allocation allowed)
// ---------------------------------------------------------------------------
__device__ float g_xw  [SEQ * BATCH * G4];
__device__ float g_hist[(SEQ + 1) * BATCH * NHID];
__device__ float g_part[KSLICES * BATCH * G4];      // 8 MB
__device__ unsigned g_flags[NCTA];                  // distributed barrier flags

// ---------------------------------------------------------------------------
// Fast activations + tf32 convert
// ---------------------------------------------------------------------------
__device__ __forceinline__ float fast_tanh(float x) {
    float y;
    asm("tanh.approx.f32 %0, %1;" : "=f"(y) : "f"(x));
    return y;
}
__device__ __forceinline__ float fast_sigmoid(float x) {
    return 0.5f * fast_tanh(0.5f * x) + 0.5f;
}
__device__ __forceinline__ uint32_t f2tf32(float f) {
    uint32_t u;
    asm("cvt.rna.tf32.f32 %0, %1;" : "=r"(u) : "f"(f));
    return u;
}

// ---------------------------------------------------------------------------
// TF32 tensor-core GEMM:  C[M,N] = A[M,K] * B[N,K]^T (+ bias[N])
// (unchanged from the 7697us passing kernel)
// ---------------------------------------------------------------------------
__global__ __launch_bounds__(256) void tf32_gemm_tn_bias(
    const float* __restrict__ A, const float* __restrict__ B,
    const float* __restrict__ bias, float* __restrict__ C,
    int M, int N, int K)
{
    __shared__ uint32_t As[2][128][20];
    __shared__ uint32_t Bs[2][128][20];

    const int tid  = threadIdx.x;
    const int bm   = blockIdx.y * 128;
    const int bn   = blockIdx.x * 128;
    const int lane = tid & 31;
    const int wid  = tid >> 5;
    const int wm   = (wid & 1) * 64;
    const int wn   = (wid >> 1) * 32;
    const int lr   = tid >> 2;
    const int lc   = (tid & 3) << 2;

    const int lq  = lane >> 2;
    const int lrm = lane & 3;

    const float* Abase = A + (size_t)(bm + lr) * K + lc;
    const float* Bbase = B + (size_t)(bn + lr) * K + lc;
    const size_t rstep = (size_t)64 * K;

    float acc[4][4][4];
#pragma unroll
    for (int i = 0; i < 4; i++)
#pragma unroll
        for (int j = 0; j < 4; j++)
#pragma unroll
            for (int r = 0; r < 4; r++) acc[i][j][r] = 0.0f;

    float4 pa[2], pb[2];

#pragma unroll
    for (int i = 0; i < 2; i++) {
        pa[i] = *(const float4*)(Abase + i * rstep);
        pb[i] = *(const float4*)(Bbase + i * rstep);
    }
#pragma unroll
    for (int i = 0; i < 2; i++) {
        const int r = lr + i * 64;
        As[0][r][lc + 0] = f2tf32(pa[i].x); As[0][r][lc + 1] = f2tf32(pa[i].y);
        As[0][r][lc + 2] = f2tf32(pa[i].z); As[0][r][lc + 3] = f2tf32(pa[i].w);
        Bs[0][r][lc + 0] = f2tf32(pb[i].x); Bs[0][r][lc + 1] = f2tf32(pb[i].y);
        Bs[0][r][lc + 2] = f2tf32(pb[i].z); Bs[0][r][lc + 3] = f2tf32(pb[i].w);
    }
    __syncthreads();

    const int NK = K >> 4;
    int buf = 0;
    for (int it = 0; it < NK; it++) {
        if (it + 1 < NK) {
            const int k0 = (it + 1) << 4;
#pragma unroll
            for (int i = 0; i < 2; i++) {
                pa[i] = *(const float4*)(Abase + i * rstep + k0);
                pb[i] = *(const float4*)(Bbase + i * rstep + k0);
            }
        }
#pragma unroll
        for (int ks = 0; ks < 2; ks++) {
            const int k0 = ks * 8;
            uint32_t a[4][4], b[4][2];
#pragma unroll
            for (int fm = 0; fm < 4; fm++) {
                const int r = wm + fm * 16 + lq;
                a[fm][0] = As[buf][r][k0 + lrm];
                a[fm][1] = As[buf][r + 8][k0 + lrm];
                a[fm][2] = As[buf][r][k0 + lrm + 4];
                a[fm][3] = As[buf][r + 8][k0 + lrm + 4];
            }
#pragma unroll
            for (int fn = 0; fn < 4; fn++) {
                const int n = wn + fn * 8 + lq;
                b[fn][0] = Bs[buf][n][k0 + lrm];
                b[fn][1] = Bs[buf][n][k0 + lrm + 4];
            }
#pragma unroll
            for (int fm = 0; fm < 4; fm++)
#pragma unroll
                for (int fn = 0; fn < 4; fn++) {
                    asm volatile(
                        "mma.sync.aligned.m16n8k8.row.col.f32.tf32.tf32.f32 "
                        "{%0,%1,%2,%3}, {%4,%5,%6,%7}, {%8,%9}, {%0,%1,%2,%3};\n"
                        : "+f"(acc[fm][fn][0]), "+f"(acc[fm][fn][1]),
                          "+f"(acc[fm][fn][2]), "+f"(acc[fm][fn][3])
                        : "r"(a[fm][0]), "r"(a[fm][1]), "r"(a[fm][2]), "r"(a[fm][3]),
                          "r"(b[fn][0]), "r"(b[fn][1]));
                }
        }
        if (it + 1 < NK) {
            const int nb2 = buf ^ 1;
#pragma unroll
            for (int i = 0; i < 2; i++) {
                const int r = lr + i * 64;
                As[nb2][r][lc + 0] = f2tf32(pa[i].x); As[nb2][r][lc + 1] = f2tf32(pa[i].y);
                As[nb2][r][lc + 2] = f2tf32(pa[i].z); As[nb2][r][lc + 3] = f2tf32(pa[i].w);
                Bs[nb2][r][lc + 0] = f2tf32(pb[i].x); Bs[nb2][r][lc + 1] = f2tf32(pb[i].y);
                Bs[nb2][r][lc + 2] = f2tf32(pb[i].z); Bs[nb2][r][lc + 3] = f2tf32(pb[i].w);
            }
        }
        __syncthreads();
        buf ^= 1;
    }

#pragma unroll
    for (int fm = 0; fm < 4; fm++) {
        const int row = bm + wm + fm * 16 + lq;
#pragma unroll
        for (int fn = 0; fn < 4; fn++) {
            const int col = bn + wn + fn * 8 + lrm * 2;
            float bx = 0.0f, by = 0.0f;
            if (bias) { bx = bias[col]; by = bias[col + 1]; }
            float2 v0 = make_float2(acc[fm][fn][0] + bx, acc[fm][fn][1] + by);
            float2 v1 = make_float2(acc[fm][fn][2] + bx, acc[fm][fn][3] + by);
            *(float2*)(C + (size_t)row * N + col) = v0;
            *(float2*)(C + (size_t)(row + 8) * N + col) = v1;
        }
    }
}

// ---------------------------------------------------------------------------
// Persistent LSTM recurrence — phase A on tf32 mma.sync, occupancy 2.
// Distributed-flag grid barrier: each CTA release-stores its epoch into its
// own flag slot (no atomic serialization); every thread polls 2 flags.
// ---------------------------------------------------------------------------
extern __shared__ uint32_t smem_u32[];

__device__ __forceinline__ void grid_barrier(unsigned epoch) {
    __syncthreads();
    if (threadIdx.x == 0) {
        __threadfence();                                   // release
        *((volatile unsigned*)&g_flags[blockIdx.x]) = epoch;
    }
    const int i0 = threadIdx.x;
    const int i1 = threadIdx.x + PERS_THREADS;
    while (*((volatile unsigned*)&g_flags[i0]) < epoch) { }
    while (*((volatile unsigned*)&g_flags[i1]) < epoch) { }
    __threadfence();                                       // acquire
    __syncthreads();
}

__global__ void __launch_bounds__(PERS_THREADS, 2)
lstm_persistent(const float* __restrict__ xw,
                const float* __restrict__ w_h,
                const float* __restrict__ c0,
                float* __restrict__ hist,
                float* __restrict__ part,
                float* __restrict__ c_out)
{
    uint32_t* ws = smem_u32;             // [128 n][TS_STRIDE]
    uint32_t* hs = smem_u32 + WSU_U32;   // [64 b][TS_STRIDE]

    const int tid = threadIdx.x;
    const int nb  = blockIdx.x & (NBLK - 1);
    const int ks  = blockIdx.x >> 5;      // 0..7
    const int bn  = nb * 128;
    const int kbase = ks * KSL;
    const int lane = tid & 31;
    const int wid  = tid >> 5;
    const int lq   = lane >> 2;
    const int lrm  = lane & 3;

    // --- cache w_h slice [128 n x 128 k] as tf32, row-major [n][k] ---
    for (int idx = tid; idx < 128 * (KSL / 4); idx += PERS_THREADS) {
        const int r  = idx >> 5;          // n row 0..127
        const int kq = idx & 31;          // float4 along k
        float4 v = *(const float4*)(w_h + (size_t)(bn + r) * NHID + kbase + kq * 4);
        uint32_t* d = ws + r * TS_STRIDE + kq * 4;
        d[0] = f2tf32(v.x); d[1] = f2tf32(v.y);
        d[2] = f2tf32(v.z); d[3] = f2tf32(v.w);
    }

    // --- fixed gate-output ownership: 2 consecutive hidden elems ---
    const int gt = blockIdx.x * PERS_THREADS + tid;   // 0..32767
    const int e2 = gt * 2;                            // 0..65534
    const int gb = e2 >> 10;                          // batch row
    const int gn = e2 & 1023;                         // hidden index (even)
    float2 creg = *(const float2*)(c0 + e2);

    unsigned epoch = 0;

    for (int t = 0; t < SEQ; t++) {
        // --- load h[t] slice [64 b x 128 k] as tf32, row-major [b][k] ---
        const float* h_t = hist + (size_t)t * (BATCH * NHID);
        for (int idx = tid; idx < BATCH * (KSL / 4); idx += PERS_THREADS) {
            const int r  = idx >> 5;      // b row 0..63
            const int kq = idx & 31;
            float4 v = *(const float4*)(h_t + (size_t)r * NHID + kbase + kq * 4);
            uint32_t* d = hs + r * TS_STRIDE + kq * 4;
            d[0] = f2tf32(v.x); d[1] = f2tf32(v.y);
            d[2] = f2tf32(v.z); d[3] = f2tf32(v.w);
        }

        // --- hoisted xw_t loads: overlap DRAM latency with phase-A MMAs ---
        const float* xw_t = xw + (size_t)t * BATCH * G4 + (size_t)gb * G4 + gn;
        float2 ai = *(const float2*)(xw_t);
        float2 af = *(const float2*)(xw_t + 1024);
        float2 ao = *(const float2*)(xw_t + 2048);
        float2 ag = *(const float2*)(xw_t + 3072);

        __syncthreads();

        // --- phase A: 64 x 128 x 128 via mma.sync tf32 ---
        float acc[4][4][4];
#pragma unroll
        for (int i = 0; i < 4; i++)
#pragma unroll
            for (int j = 0; j < 4; j++)
#pragma unroll
                for (int r = 0; r < 4; r++) acc[i][j][r] = 0.0f;

        for (int k0 = 0; k0 < KSL; k0 += 8) {
            uint32_t a[4][4], b[4][2];
#pragma unroll
            for (int fm = 0; fm < 4; fm++) {
                const int r = fm * 16 + lq;
                a[fm][0] = hs[r * TS_STRIDE + k0 + lrm];
                a[fm][1] = hs[(r + 8) * TS_STRIDE + k0 + lrm];
                a[fm][2] = hs[r * TS_STRIDE + k0 + lrm + 4];
                a[fm][3] = hs[(r + 8) * TS_STRIDE + k0 + lrm + 4];
            }
#pragma unroll
            for (int fn = 0; fn < 4; fn++) {
                const int n = wid * 32 + fn * 8 + lq;
                b[fn][0] = ws[n * TS_STRIDE + k0 + lrm];
                b[fn][1] = ws[n * TS_STRIDE + k0 + lrm + 4];
            }
#pragma unroll
            for (int fm = 0; fm < 4; fm++)
#pragma unroll
                for (int fn = 0; fn < 4; fn++) {
                    asm volatile(
                        "mma.sync.aligned.m16n8k8.row.col.f32.tf32.tf32.f32 "
                        "{%0,%1,%2,%3}, {%4,%5,%6,%7}, {%8,%9}, {%0,%1,%2,%3};\n"
                        : "+f"(acc[fm][fn][0]), "+f"(acc[fm][fn][1]),
                          "+f"(acc[fm][fn][2]), "+f"(acc[fm][fn][3])
                        : "r"(a[fm][0]), "r"(a[fm][1]), "r"(a[fm][2]), "r"(a[fm][3]),
                          "r"(b[fn][0]), "r"(b[fn][1]));
                }
        }

        // write partials: part[ks][b][bn + n]
#pragma unroll
        for (int fm = 0; fm < 4; fm++) {
            const int row0 = fm * 16 + lq;
#pragma unroll
            for (int fn = 0; fn < 4; fn++) {
                const int col = bn + wid * 32 + fn * 8 + lrm * 2;
                float* p0 = part + ((size_t)ks * BATCH + row0) * G4 + col;
                float* p1 = part + ((size_t)ks * BATCH + row0 + 8) * G4 + col;
                *(float2*)p0 = make_float2(acc[fm][fn][0], acc[fm][fn][1]);
                *(float2*)p1 = make_float2(acc[fm][fn][2], acc[fm][fn][3]);
            }
        }

        // --- grid barrier 1: partials visible ---
        epoch++;
        grid_barrier(epoch);

        // --- phase B: gates for my 2 elements (fp32) ---
        {
#pragma unroll
            for (int s = 0; s < KSLICES; s++) {
                const float* p = part + (size_t)s * BATCH * G4 + (size_t)gb * G4 + gn;
                float2 v;
                v = __ldcg((const float2*)(p));
                ai.x += v.x; ai.y += v.y;
                v = __ldcg((const float2*)(p + 1024));
                af.x += v.x; af.y += v.y;
                v = __ldcg((const float2*)(p + 2048));
                ao.x += v.x; ao.y += v.y;
                v = __ldcg((const float2*)(p + 3072));
                ag.x += v.x; ag.y += v.y;
            }
            float2 hv;
            {
                float i0 = fast_sigmoid(ai.x), f0 = fast_sigmoid(af.x);
                float o0 = fast_sigmoid(ao.x), g0 = fast_tanh(ag.x);
                creg.x = f0 * creg.x + i0 * g0;  hv.x = o0 * fast_tanh(creg.x);
            }
            {
                float i0 = fast_sigmoid(ai.y), f0 = fast_sigmoid(af.y);
                float o0 = fast_sigmoid(ao.y), g0 = fast_tanh(ag.y);
                creg.y = f0 * creg.y + i0 * g0;  hv.y = o0 * fast_tanh(creg.y);
            }
            *(float2*)(hist + (size_t)(t + 1) * (BATCH * NHID) + e2) = hv;
        }

        // --- grid barrier 2: hist[t+1] visible before next step ---
        epoch++;
        grid_barrier(epoch);
    }

    *(float2*)(c_out + e2) = creg;
}

// ---------------------------------------------------------------------------
// Launch
// ---------------------------------------------------------------------------
extern "C" void kernel_launch(void* const* d_in, const int* in_sizes, int n_in,
                              void* d_out, int out_size)
{
    (void)in_sizes; (void)n_in; (void)out_size;
    const float* x    = (const float*)d_in[0];
    const float* h0   = (const float*)d_in[1];
    const float* c0   = (const float*)d_in[2];
    const float* w_x  = (const float*)d_in[3];
    const float* w_h  = (const float*)d_in[4];
    const float* bias = (const float*)d_in[5];
    const float* w_o  = (const float*)d_in[6];

    float* pred  = (float*)d_out;
    float* h_out = pred + (size_t)SEQ * BATCH * NHID;
    float* c_out = h_out + (size_t)BATCH * NHID;

    float *xw, *hist, *part; unsigned* flags;
    cudaGetSymbolAddress((void**)&xw,    g_xw);
    cudaGetSymbolAddress((void**)&hist,  g_hist);
    cudaGetSymbolAddress((void**)&part,  g_part);
    cudaGetSymbolAddress((void**)&flags, g_flags);

    cudaFuncSetAttribute(lstm_persistent,
                         cudaFuncAttributeMaxDynamicSharedMemorySize,
                         PERS_SMEM_BYTES);

    const size_t state_bytes = (size_t)BATCH * NHID * sizeof(float);

    cudaMemsetAsync(flags, 0, NCTA * sizeof(unsigned));
    cudaMemcpyAsync(hist, h0, state_bytes, cudaMemcpyDeviceToDevice);

    // xw = x @ w_x^T + bias   (tf32 tensor cores)
    {
        dim3 grid(G4 / 128, (SEQ * BATCH) / 128);
        tf32_gemm_tn_bias<<<grid, 256>>>(x, w_x, bias, xw, SEQ * BATCH, G4, NIN);
    }

    // recurrence (persistent, phase A on tensor cores, occ 2, flag barrier)
    lstm_persistent<<<NCTA, PERS_THREADS, PERS_SMEM_BYTES>>>(
        xw, w_h, c0, hist, part, c_out);

    // pred = hist[1..] @ w_o^T   (tf32 tensor cores)
    {
        dim3 grid(NHID / 128, (SEQ * BATCH) / 128);
        tf32_gemm_tn_bias<<<grid, 256>>>(hist + (size_t)BATCH * NHID, w_o, nullptr,
                                         pred, SEQ * BATCH, NHID, NHID);
    }

    cudaMemcpyAsync(h_out, hist + (size_t)SEQ * BATCH * NHID, state_bytes,
                    cudaMemcpyDeviceToDevice);
}

// round 16
// speedup vs baseline: 1.9467x; 1.9467x over previous
#include <cuda_runtime.h>
#include <cstdint>
#include <cstddef>

// ---------------------------------------------------------------------------
// Problem constants
// ---------------------------------------------------------------------------
#define SEQ   512
#define BATCH 64
#define NHID  1024
#define NIN   1024
#define G4    4096   // 4*NHID

// Persistent recurrence: 32 n-blocks (128 wide) x 4 k-slices (256 deep)
// = 128 CTAs x 256 threads (8 warps), ~206KB smem -> occ 1.
// 128 CTAs < 148 SMs -> one CTA per SM, BALANCED, co-resident (barrier-safe).
#define NBLK   32
#define KSLICES 4
#define KSL    256
#define NCTA   128
#define PERS_THREADS 256

// tf32 smem tiles, stride 268 u32 (268 mod 32 = 12 -> frag banks 12*lq+lrm
// all distinct mod 32 -> conflict-free fragment LDS)
#define TS_STRIDE 268
#define WSU_U32 (128 * TS_STRIDE)   // w_h slice [128 n][256 k]
#define HSU_U32 (64  * TS_STRIDE)   // h   slice [64 b][256 k]
#define PERS_SMEM_BYTES ((WSU_U32 + HSU_U32) * 4)  // 205824 < 227KB

// ---------------------------------------------------------------------------
// Scratch (static device globals; no dynamic allocation allowed)
// ---------------------------------------------------------------------------
__device__ float g_xw  [SEQ * BATCH * G4];
__device__ float g_hist[(SEQ + 1) * BATCH * NHID];
__device__ float g_part[KSLICES * BATCH * G4];      // 4 MB
__device__ unsigned g_bar;                          // central barrier counter

// ---------------------------------------------------------------------------
// Fast activations + tf32 convert
// ---------------------------------------------------------------------------
__device__ __forceinline__ float fast_tanh(float x) {
    float y;
    asm("tanh.approx.f32 %0, %1;" : "=f"(y) : "f"(x));
    return y;
}
__device__ __forceinline__ float fast_sigmoid(float x) {
    return 0.5f * fast_tanh(0.5f * x) + 0.5f;
}
__device__ __forceinline__ uint32_t f2tf32(float f) {
    uint32_t u;
    asm("cvt.rna.tf32.f32 %0, %1;" : "=r"(u) : "f"(f));
    return u;
}

// ---------------------------------------------------------------------------
// TF32 tensor-core GEMM:  C[M,N] = A[M,K] * B[N,K]^T (+ bias[N])
// (unchanged from the 7697us passing kernel)
// ---------------------------------------------------------------------------
__global__ __launch_bounds__(256) void tf32_gemm_tn_bias(
    const float* __restrict__ A, const float* __restrict__ B,
    const float* __restrict__ bias, float* __restrict__ C,
    int M, int N, int K)
{
    __shared__ uint32_t As[2][128][20];
    __shared__ uint32_t Bs[2][128][20];

    const int tid  = threadIdx.x;
    const int bm   = blockIdx.y * 128;
    const int bn   = blockIdx.x * 128;
    const int lane = tid & 31;
    const int wid  = tid >> 5;
    const int wm   = (wid & 1) * 64;
    const int wn   = (wid >> 1) * 32;
    const int lr   = tid >> 2;
    const int lc   = (tid & 3) << 2;

    const int lq  = lane >> 2;
    const int lrm = lane & 3;

    const float* Abase = A + (size_t)(bm + lr) * K + lc;
    const float* Bbase = B + (size_t)(bn + lr) * K + lc;
    const size_t rstep = (size_t)64 * K;

    float acc[4][4][4];
#pragma unroll
    for (int i = 0; i < 4; i++)
#pragma unroll
        for (int j = 0; j < 4; j++)
#pragma unroll
            for (int r = 0; r < 4; r++) acc[i][j][r] = 0.0f;

    float4 pa[2], pb[2];

#pragma unroll
    for (int i = 0; i < 2; i++) {
        pa[i] = *(const float4*)(Abase + i * rstep);
        pb[i] = *(const float4*)(Bbase + i * rstep);
    }
#pragma unroll
    for (int i = 0; i < 2; i++) {
        const int r = lr + i * 64;
        As[0][r][lc + 0] = f2tf32(pa[i].x); As[0][r][lc + 1] = f2tf32(pa[i].y);
        As[0][r][lc + 2] = f2tf32(pa[i].z); As[0][r][lc + 3] = f2tf32(pa[i].w);
        Bs[0][r][lc + 0] = f2tf32(pb[i].x); Bs[0][r][lc + 1] = f2tf32(pb[i].y);
        Bs[0][r][lc + 2] = f2tf32(pb[i].z); Bs[0][r][lc + 3] = f2tf32(pb[i].w);
    }
    __syncthreads();

    const int NK = K >> 4;
    int buf = 0;
    for (int it = 0; it < NK; it++) {
        if (it + 1 < NK) {
            const int k0 = (it + 1) << 4;
#pragma unroll
            for (int i = 0; i < 2; i++) {
                pa[i] = *(const float4*)(Abase + i * rstep + k0);
                pb[i] = *(const float4*)(Bbase + i * rstep + k0);
            }
        }
#pragma unroll
        for (int ks = 0; ks < 2; ks++) {
            const int k0 = ks * 8;
            uint32_t a[4][4], b[4][2];
#pragma unroll
            for (int fm = 0; fm < 4; fm++) {
                const int r = wm + fm * 16 + lq;
                a[fm][0] = As[buf][r][k0 + lrm];
                a[fm][1] = As[buf][r + 8][k0 + lrm];
                a[fm][2] = As[buf][r][k0 + lrm + 4];
                a[fm][3] = As[buf][r + 8][k0 + lrm + 4];
            }
#pragma unroll
            for (int fn = 0; fn < 4; fn++) {
                const int n = wn + fn * 8 + lq;
                b[fn][0] = Bs[buf][n][k0 + lrm];
                b[fn][1] = Bs[buf][n][k0 + lrm + 4];
            }
#pragma unroll
            for (int fm = 0; fm < 4; fm++)
#pragma unroll
                for (int fn = 0; fn < 4; fn++) {
                    asm volatile(
                        "mma.sync.aligned.m16n8k8.row.col.f32.tf32.tf32.f32 "
                        "{%0,%1,%2,%3}, {%4,%5,%6,%7}, {%8,%9}, {%0,%1,%2,%3};\n"
                        : "+f"(acc[fm][fn][0]), "+f"(acc[fm][fn][1]),
                          "+f"(acc[fm][fn][2]), "+f"(acc[fm][fn][3])
                        : "r"(a[fm][0]), "r"(a[fm][1]), "r"(a[fm][2]), "r"(a[fm][3]),
                          "r"(b[fn][0]), "r"(b[fn][1]));
                }
        }
        if (it + 1 < NK) {
            const int nb2 = buf ^ 1;
#pragma unroll
            for (int i = 0; i < 2; i++) {
                const int r = lr + i * 64;
                As[nb2][r][lc + 0] = f2tf32(pa[i].x); As[nb2][r][lc + 1] = f2tf32(pa[i].y);
                As[nb2][r][lc + 2] = f2tf32(pa[i].z); As[nb2][r][lc + 3] = f2tf32(pa[i].w);
                Bs[nb2][r][lc + 0] = f2tf32(pb[i].x); Bs[nb2][r][lc + 1] = f2tf32(pb[i].y);
                Bs[nb2][r][lc + 2] = f2tf32(pb[i].z); Bs[nb2][r][lc + 3] = f2tf32(pb[i].w);
            }
        }
        __syncthreads();
        buf ^= 1;
    }

#pragma unroll
    for (int fm = 0; fm < 4; fm++) {
        const int row = bm + wm + fm * 16 + lq;
#pragma unroll
        for (int fn = 0; fn < 4; fn++) {
            const int col = bn + wn + fn * 8 + lrm * 2;
            float bx = 0.0f, by = 0.0f;
            if (bias) { bx = bias[col]; by = bias[col + 1]; }
            float2 v0 = make_float2(acc[fm][fn][0] + bx, acc[fm][fn][1] + by);
            float2 v1 = make_float2(acc[fm][fn][2] + bx, acc[fm][fn][3] + by);
            *(float2*)(C + (size_t)row * N + col) = v0;
            *(float2*)(C + (size_t)(row + 8) * N + col) = v1;
        }
    }
}

// ---------------------------------------------------------------------------
// Persistent LSTM recurrence — phase A tf32 mma.sync, 128 CTAs x 256 threads.
// One CTA per SM (balanced). Central-atomic barrier (tid0 arrive + poll) —
// the measured-good design; all-thread flag polling (R14) regressed 81%.
// ---------------------------------------------------------------------------
extern __shared__ uint32_t smem_u32[];

__device__ __forceinline__ void grid_barrier(unsigned target) {
    __syncthreads();
    if (threadIdx.x == 0) {
        __threadfence();                      // release
        atomicAdd(&g_bar, 1u);
        while (*(volatile unsigned*)&g_bar < target) { }
        __threadfence();                      // acquire
    }
    __syncthreads();
}

__global__ void __launch_bounds__(PERS_THREADS, 1)
lstm_persistent(const float* __restrict__ xw,
                const float* __restrict__ w_h,
                const float* __restrict__ c0,
                float* __restrict__ hist,
                float* __restrict__ part,
                float* __restrict__ c_out)
{
    uint32_t* ws = smem_u32;             // [128 n][TS_STRIDE]
    uint32_t* hs = smem_u32 + WSU_U32;   // [64 b][TS_STRIDE]

    const int tid = threadIdx.x;
    const int nb  = blockIdx.x & (NBLK - 1);
    const int ks  = blockIdx.x >> 5;      // 0..3
    const int bn  = nb * 128;
    const int kbase = ks * KSL;
    const int lane = tid & 31;
    const int wid  = tid >> 5;            // 0..7
    const int wm2  = (wid & 1) * 32;      // warp m offset (2 m-groups)
    const int wn2  = (wid >> 1) * 32;     // warp n offset (4 n-groups)
    const int lq   = lane >> 2;
    const int lrm  = lane & 3;

    // --- cache w_h slice [128 n x 256 k] as tf32, row-major [n][k] ---
    for (int idx = tid; idx < 128 * (KSL / 4); idx += PERS_THREADS) {
        const int r  = idx >> 6;          // n row 0..127
        const int kq = idx & 63;          // float4 along k
        float4 v = *(const float4*)(w_h + (size_t)(bn + r) * NHID + kbase + kq * 4);
        uint32_t* d = ws + r * TS_STRIDE + kq * 4;
        d[0] = f2tf32(v.x); d[1] = f2tf32(v.y);
        d[2] = f2tf32(v.z); d[3] = f2tf32(v.w);
    }

    // --- fixed gate-output ownership: 2 consecutive hidden elems ---
    const int gt = blockIdx.x * PERS_THREADS + tid;   // 0..32767
    const int e2 = gt * 2;                            // 0..65534
    const int gb = e2 >> 10;                          // batch row
    const int gn = e2 & 1023;                         // hidden index (even)
    float2 creg = *(const float2*)(c0 + e2);

    unsigned epoch = 0;

    for (int t = 0; t < SEQ; t++) {
        // --- load h[t] slice [64 b x 256 k] as tf32, row-major [b][k] ---
        const float* h_t = hist + (size_t)t * (BATCH * NHID);
        for (int idx = tid; idx < BATCH * (KSL / 4); idx += PERS_THREADS) {
            const int r  = idx >> 6;      // b row 0..63
            const int kq = idx & 63;
            float4 v = *(const float4*)(h_t + (size_t)r * NHID + kbase + kq * 4);
            uint32_t* d = hs + r * TS_STRIDE + kq * 4;
            d[0] = f2tf32(v.x); d[1] = f2tf32(v.y);
            d[2] = f2tf32(v.z); d[3] = f2tf32(v.w);
        }

        // --- hoisted xw_t loads: overlap DRAM latency with phase-A MMAs ---
        const float* xw_t = xw + (size_t)t * BATCH * G4 + (size_t)gb * G4 + gn;
        float2 ai = *(const float2*)(xw_t);
        float2 af = *(const float2*)(xw_t + 1024);
        float2 ao = *(const float2*)(xw_t + 2048);
        float2 ag = *(const float2*)(xw_t + 3072);

        __syncthreads();

        // --- phase A: 64 x 128 x 256 via mma.sync tf32, 8 warps (2m x 4n) ---
        float acc[2][4][4];
#pragma unroll
        for (int i = 0; i < 2; i++)
#pragma unroll
            for (int j = 0; j < 4; j++)
#pragma unroll
                for (int r = 0; r < 4; r++) acc[i][j][r] = 0.0f;

        for (int k0 = 0; k0 < KSL; k0 += 8) {
            uint32_t a[2][4], b[4][2];
#pragma unroll
            for (int fm = 0; fm < 2; fm++) {
                const int r = wm2 + fm * 16 + lq;
                a[fm][0] = hs[r * TS_STRIDE + k0 + lrm];
                a[fm][1] = hs[(r + 8) * TS_STRIDE + k0 + lrm];
                a[fm][2] = hs[r * TS_STRIDE + k0 + lrm + 4];
                a[fm][3] = hs[(r + 8) * TS_STRIDE + k0 + lrm + 4];
            }
#pragma unroll
            for (int fn = 0; fn < 4; fn++) {
                const int n = wn2 + fn * 8 + lq;
                b[fn][0] = ws[n * TS_STRIDE + k0 + lrm];
                b[fn][1] = ws[n * TS_STRIDE + k0 + lrm + 4];
            }
#pragma unroll
            for (int fm = 0; fm < 2; fm++)
#pragma unroll
                for (int fn = 0; fn < 4; fn++) {
                    asm volatile(
                        "mma.sync.aligned.m16n8k8.row.col.f32.tf32.tf32.f32 "
                        "{%0,%1,%2,%3}, {%4,%5,%6,%7}, {%8,%9}, {%0,%1,%2,%3};\n"
                        : "+f"(acc[fm][fn][0]), "+f"(acc[fm][fn][1]),
                          "+f"(acc[fm][fn][2]), "+f"(acc[fm][fn][3])
                        : "r"(a[fm][0]), "r"(a[fm][1]), "r"(a[fm][2]), "r"(a[fm][3]),
                          "r"(b[fn][0]), "r"(b[fn][1]));
                }
        }

        // write partials: part[ks][b][bn + n]
#pragma unroll
        for (int fm = 0; fm < 2; fm++) {
            const int row0 = wm2 + fm * 16 + lq;
#pragma unroll
            for (int fn = 0; fn < 4; fn++) {
                const int col = bn + wn2 + fn * 8 + lrm * 2;
                float* p0 = part + ((size_t)ks * BATCH + row0) * G4 + col;
                float* p1 = part + ((size_t)ks * BATCH + row0 + 8) * G4 + col;
                *(float2*)p0 = make_float2(acc[fm][fn][0], acc[fm][fn][1]);
                *(float2*)p1 = make_float2(acc[fm][fn][2], acc[fm][fn][3]);
            }
        }

        // --- grid barrier 1: partials visible ---
        epoch++;
        grid_barrier(epoch * NCTA);

        // --- phase B: gates for my 2 elements (fp32) ---
        {
#pragma unroll
            for (int s = 0; s < KSLICES; s++) {
                const float* p = part + (size_t)s * BATCH * G4 + (size_t)gb * G4 + gn;
                float2 v;
                v = __ldcg((const float2*)(p));
                ai.x += v.x; ai.y += v.y;
                v = __ldcg((const float2*)(p + 1024));
                af.x += v.x; af.y += v.y;
                v = __ldcg((const float2*)(p + 2048));
                ao.x += v.x; ao.y += v.y;
                v = __ldcg((const float2*)(p + 3072));
                ag.x += v.x; ag.y += v.y;
            }
            float2 hv;
            {
                float i0 = fast_sigmoid(ai.x), f0 = fast_sigmoid(af.x);
                float o0 = fast_sigmoid(ao.x), g0 = fast_tanh(ag.x);
                creg.x = f0 * creg.x + i0 * g0;  hv.x = o0 * fast_tanh(creg.x);
            }
            {
                float i0 = fast_sigmoid(ai.y), f0 = fast_sigmoid(af.y);
                float o0 = fast_sigmoid(ao.y), g0 = fast_tanh(ag.y);
                creg.y = f0 * creg.y + i0 * g0;  hv.y = o0 * fast_tanh(creg.y);
            }
            *(float2*)(hist + (size_t)(t + 1) * (BATCH * NHID) + e2) = hv;
        }

        // --- grid barrier 2: hist[t+1] visible before next step ---
        epoch++;
        grid_barrier(epoch * NCTA);
    }

    *(float2*)(c_out + e2) = creg;
}

// ---------------------------------------------------------------------------
// Launch
// ---------------------------------------------------------------------------
extern "C" void kernel_launch(void* const* d_in, const int* in_sizes, int n_in,
                              void* d_out, int out_size)
{
    (void)in_sizes; (void)n_in; (void)out_size;
    const float* x    = (const float*)d_in[0];
    const float* h0   = (const float*)d_in[1];
    const float* c0   = (const float*)d_in[2];
    const float* w_x  = (const float*)d_in[3];
    const float* w_h  = (const float*)d_in[4];
    const float* bias = (const float*)d_in[5];
    const float* w_o  = (const float*)d_in[6];

    float* pred  = (float*)d_out;
    float* h_out = pred + (size_t)SEQ * BATCH * NHID;
    float* c_out = h_out + (size_t)BATCH * NHID;

    float *xw, *hist, *part; unsigned* bar;
    cudaGetSymbolAddress((void**)&xw,   g_xw);
    cudaGetSymbolAddress((void**)&hist, g_hist);
    cudaGetSymbolAddress((void**)&part, g_part);
    cudaGetSymbolAddress((void**)&bar,  g_bar);

    cudaFuncSetAttribute(lstm_persistent,
                         cudaFuncAttributeMaxDynamicSharedMemorySize,
                         PERS_SMEM_BYTES);

    const size_t state_bytes = (size_t)BATCH * NHID * sizeof(float);

    cudaMemsetAsync(bar, 0, sizeof(unsigned));
    cudaMemcpyAsync(hist, h0, state_bytes, cudaMemcpyDeviceToDevice);

    // xw = x @ w_x^T + bias   (tf32 tensor cores)
    {
        dim3 grid(G4 / 128, (SEQ * BATCH) / 128);
        tf32_gemm_tn_bias<<<grid, 256>>>(x, w_x, bias, xw, SEQ * BATCH, G4, NIN);
    }

    // recurrence (persistent, balanced 128 CTAs x 256 thr, central barrier)
    lstm_persistent<<<NCTA, PERS_THREADS, PERS_SMEM_BYTES>>>(
        xw, w_h, c0, hist, part, c_out);

    // pred = hist[1..] @ w_o^T   (tf32 tensor cores)
    {
        dim3 grid(NHID / 128, (SEQ * BATCH) / 128);
        tf32_gemm_tn_bias<<<grid, 256>>>(hist + (size_t)BATCH * NHID, w_o, nullptr,
                                         pred, SEQ * BATCH, NHID, NHID);
    }

    cudaMemcpyAsync(h_out, hist + (size_t)SEQ * BATCH * NHID, state_bytes,
                    cudaMemcpyDeviceToDevice);
}